// round 9
// baseline (speedup 1.0000x reference)
#include <cuda_runtime.h>
#include <cuda_bf16.h>
#include <cstdint>

#define N_NODES 100000
#define E_MAX   1200000
#define D 64

#define SCAN_CHUNK 1024
#define N_CHUNKS   ((N_NODES + SCAN_CHUNK - 1) / SCAN_CHUNK)   // 98
#define N_PADDED   (N_CHUNKS * SCAN_CHUNK)                     // 100352

// Device scratch (no allocations allowed).
__device__ float g_h[N_NODES * D];              // (x@W) * norm_src, 25.6 MB
__device__ int   g_deg_out[N_NODES];
__device__ int   g_deg_in[N_NODES];
__device__ int   g_rowptr[N_PADDED + 1];
__device__ int   g_cursor[N_NODES];
__device__ int   g_scan_val[N_CHUNKS];          // -1 = not published, else chunk sum
__device__ int   g_csrc[E_MAX];                 // src node per CSR slot (grouped by dst)

// ---------------------------------------------------------------------------
__global__ void init_kernel() {
    int i = blockIdx.x * blockDim.x + threadIdx.x;
    if (i < N_NODES) { g_deg_out[i] = 0; g_deg_in[i] = 0; }
    if (i < N_CHUNKS) g_scan_val[i] = -1;
}

// ---------------------------------------------------------------------------
__global__ void degree_kernel(const int* __restrict__ src,
                              const int* __restrict__ dst, int E) {
    int i = blockIdx.x * blockDim.x + threadIdx.x;
    if (i < E) {
        atomicAdd(&g_deg_out[src[i]], 1);
        atomicAdd(&g_deg_in [dst[i]], 1);
    }
}

// ---------------------------------------------------------------------------
// Single-pass exclusive scan of deg_in with decoupled lookback (98 blocks, one wave).
__global__ void __launch_bounds__(256) scan_kernel() {
    __shared__ int sh[256];
    const int t    = threadIdx.x;
    const int bid  = blockIdx.x;
    const int base = bid * SCAN_CHUNK + t * 4;

    int v0 = (base + 0 < N_NODES) ? g_deg_in[base + 0] : 0;
    int v1 = (base + 1 < N_NODES) ? g_deg_in[base + 1] : 0;
    int v2 = (base + 2 < N_NODES) ? g_deg_in[base + 2] : 0;
    int v3 = (base + 3 < N_NODES) ? g_deg_in[base + 3] : 0;
    int s  = v0 + v1 + v2 + v3;

    sh[t] = s; __syncthreads();
    #pragma unroll
    for (int off = 1; off < 256; off <<= 1) {
        int x = (t >= off) ? sh[t - off] : 0;
        __syncthreads();
        sh[t] += x;
        __syncthreads();
    }
    const int excl = sh[t] - s;
    if (t == 255) atomicExch(&g_scan_val[bid], sh[255]);

    int part = 0;
    if (t < bid) {
        int v;
        do { v = atomicAdd(&g_scan_val[t], 0); } while (v < 0);
        part = v;
    }
    __syncthreads();
    sh[t] = part; __syncthreads();
    #pragma unroll
    for (int off = 128; off > 0; off >>= 1) {
        if (t < off) sh[t] += sh[t + off];
        __syncthreads();
    }
    const int off0 = sh[0];

    int r0 = off0 + excl;
    g_rowptr[base + 0] = r0;
    g_rowptr[base + 1] = r0 + v0;
    g_rowptr[base + 2] = r0 + v0 + v1;
    g_rowptr[base + 3] = r0 + v0 + v1 + v2;
    if (base + 0 < N_NODES) g_cursor[base + 0] = r0;
    if (base + 1 < N_NODES) g_cursor[base + 1] = r0 + v0;
    if (base + 2 < N_NODES) g_cursor[base + 2] = r0 + v0 + v1;
    if (base + 3 < N_NODES) g_cursor[base + 3] = r0 + v0 + v1 + v2;
}

// ---------------------------------------------------------------------------
__global__ void permute_kernel(const int* __restrict__ src,
                               const int* __restrict__ dst, int E) {
    int i = blockIdx.x * blockDim.x + threadIdx.x;
    if (i < E) {
        int slot = atomicAdd(&g_cursor[dst[i]], 1);
        g_csrc[slot] = src[i];
    }
}

// ---------------------------------------------------------------------------
// Packed f32x2 helpers.
__device__ __forceinline__ void fma2(unsigned long long& d,
                                     unsigned long long a,
                                     unsigned long long b) {
    asm("fma.rn.f32x2 %0, %1, %2, %0;" : "+l"(d) : "l"(a), "l"(b));
}
__device__ __forceinline__ unsigned long long pack2(float x) {
    unsigned long long r;
    asm("mov.b64 %0, {%1,%1};" : "=l"(r) : "f"(x));
    return r;
}

// ---------------------------------------------------------------------------
// h_scaled = (x @ W) * norm_src.
// 256 threads/block, tile 128 rows x 64 cols, thread = 2 rows x 16 cols.
// Same smem (51KB, 4 blocks/SM) but 2x warps -> ~50% occupancy for latency hiding.
#define XPAD 68
__global__ void __launch_bounds__(256) gemm_scale_kernel(const float* __restrict__ x,
                                                         const float* __restrict__ W) {
    __shared__ float Ws[64 * 64];        // [k][c]
    __shared__ float Xs[128 * XPAD];     // [r][k]

    const int t    = threadIdx.x;
    const int row0 = blockIdx.x * 128;
    const int rows = min(128, N_NODES - row0);

    // Load W: 1024 float4 / 256 threads = 4 each.
    {
        const float4* W4  = (const float4*)W;
        float4*       Ws4 = (float4*)Ws;
        #pragma unroll
        for (int i = 0; i < 4; i++) Ws4[t + i * 256] = W4[t + i * 256];
    }
    // Load x tile: 2048 float4 / 256 threads = 8 each.
    {
        const float4* xg = (const float4*)(x + (size_t)row0 * 64);
        #pragma unroll
        for (int i = 0; i < 8; i++) {
            int idx4 = t + i * 256;
            int r  = idx4 >> 4;
            int c4 = (idx4 & 15) * 4;
            if (r < rows)
                *(float4*)&Xs[r * XPAD + c4] = xg[idx4];
        }
    }
    __syncthreads();

    const int rg = t >> 2;              // 0..63 -> rows rg*2, rg*2+1
    const int cq = (t & 3) * 16;        // 0,16,32,48
    const int r0 = rg * 2;
    if (r0 >= rows) return;

    unsigned long long acc[2][8];
    #pragma unroll
    for (int r = 0; r < 2; r++)
        #pragma unroll
        for (int c = 0; c < 8; c++) acc[r][c] = 0ull;

    #pragma unroll 4
    for (int kq = 0; kq < 64; kq += 4) {
        float4 xr0 = *(const float4*)&Xs[(r0 + 0) * XPAD + kq];
        float4 xr1 = *(const float4*)&Xs[(r0 + 1) * XPAD + kq];
        const float* xr0f = (const float*)&xr0;
        const float* xr1f = (const float*)&xr1;

        #pragma unroll
        for (int kk = 0; kk < 4; kk++) {
            unsigned long long xv0 = pack2(xr0f[kk]);
            unsigned long long xv1 = pack2(xr1f[kk]);
            const ulonglong2* wp = (const ulonglong2*)&Ws[(kq + kk) * 64 + cq];
            ulonglong2 wa = wp[0];
            ulonglong2 wb = wp[1];
            ulonglong2 wc = wp[2];
            ulonglong2 wd = wp[3];
            fma2(acc[0][0], xv0, wa.x); fma2(acc[0][1], xv0, wa.y);
            fma2(acc[0][2], xv0, wb.x); fma2(acc[0][3], xv0, wb.y);
            fma2(acc[0][4], xv0, wc.x); fma2(acc[0][5], xv0, wc.y);
            fma2(acc[0][6], xv0, wd.x); fma2(acc[0][7], xv0, wd.y);
            fma2(acc[1][0], xv1, wa.x); fma2(acc[1][1], xv1, wa.y);
            fma2(acc[1][2], xv1, wb.x); fma2(acc[1][3], xv1, wb.y);
            fma2(acc[1][4], xv1, wc.x); fma2(acc[1][5], xv1, wc.y);
            fma2(acc[1][6], xv1, wd.x); fma2(acc[1][7], xv1, wd.y);
        }
    }

    #pragma unroll
    for (int r = 0; r < 2; r++) {
        int row = row0 + r0 + r;
        if (r0 + r >= rows) break;
        float norm = rsqrtf(fmaxf((float)g_deg_out[row], 1.f));
        float* outp = g_h + (size_t)row * 64 + cq;
        #pragma unroll
        for (int c = 0; c < 4; c++) {
            float l0, h0, l1, h1;
            asm("mov.b64 {%0,%1}, %2;" : "=f"(l0), "=f"(h0) : "l"(acc[r][2*c+0]));
            asm("mov.b64 {%0,%1}, %2;" : "=f"(l1), "=f"(h1) : "l"(acc[r][2*c+1]));
            float4 v;
            v.x = l0 * norm; v.y = h0 * norm; v.z = l1 * norm; v.w = h1 * norm;
            *(float4*)(outp + 4 * c) = v;
        }
    }
}

// ---------------------------------------------------------------------------
// Pull aggregation: one warp per dst node, lane owns 2 cols. 4-deep MLP.
__global__ void __launch_bounds__(256) aggregate_kernel(const float* __restrict__ b,
                                                        float* __restrict__ out) {
    int wg   = (blockIdx.x * blockDim.x + threadIdx.x) >> 5;
    int lane = threadIdx.x & 31;
    if (wg >= N_NODES) return;

    const int beg = g_rowptr[wg];
    const int end = g_rowptr[wg + 1];

    float2 acc0 = make_float2(0.f, 0.f);
    float2 acc1 = make_float2(0.f, 0.f);

    for (int j = beg; j < end; j += 32) {
        int n  = min(32, end - j);
        int sv = (lane < n) ? g_csrc[j + lane] : 0;
        int i  = 0;
        for (; i + 4 <= n; i += 4) {
            int u0 = __shfl_sync(0xffffffff, sv, i);
            int u1 = __shfl_sync(0xffffffff, sv, i + 1);
            int u2 = __shfl_sync(0xffffffff, sv, i + 2);
            int u3 = __shfl_sync(0xffffffff, sv, i + 3);
            float2 h0 = __ldg((const float2*)(g_h + (size_t)u0 * 64) + lane);
            float2 h1 = __ldg((const float2*)(g_h + (size_t)u1 * 64) + lane);
            float2 h2 = __ldg((const float2*)(g_h + (size_t)u2 * 64) + lane);
            float2 h3 = __ldg((const float2*)(g_h + (size_t)u3 * 64) + lane);
            acc0.x += h0.x; acc0.y += h0.y;
            acc1.x += h1.x; acc1.y += h1.y;
            acc0.x += h2.x; acc0.y += h2.y;
            acc1.x += h3.x; acc1.y += h3.y;
        }
        for (; i < n; i++) {
            int u = __shfl_sync(0xffffffff, sv, i);
            float2 h = __ldg((const float2*)(g_h + (size_t)u * 64) + lane);
            acc0.x += h.x; acc0.y += h.y;
        }
    }

    float  norm = rsqrtf(fmaxf((float)(end - beg), 1.f));
    float2 bb   = *(const float2*)(b + lane * 2);
    float2 r;
    r.x = fmaxf((acc0.x + acc1.x) * norm + bb.x, 0.f);
    r.y = fmaxf((acc0.y + acc1.y) * norm + bb.y, 0.f);
    *(float2*)(out + (size_t)wg * 64 + lane * 2) = r;
}

// ---------------------------------------------------------------------------
extern "C" void kernel_launch(void* const* d_in, const int* in_sizes, int n_in,
                              void* d_out, int out_size) {
    const float* x   = (const float*)d_in[0];
    const float* W   = (const float*)d_in[1];
    const float* b   = (const float*)d_in[2];
    const int*   src = (const int*)  d_in[3];
    const int*   dst = (const int*)  d_in[4];
    const int    E   = in_sizes[3];

    float* out = (float*)d_out;

    static cudaStream_t s2 = nullptr;
    static cudaEvent_t  evA = nullptr, evB = nullptr;
    if (s2 == nullptr) {
        cudaStreamCreateWithFlags(&s2, cudaStreamNonBlocking);
        cudaEventCreateWithFlags(&evA, cudaEventDisableTiming);
        cudaEventCreateWithFlags(&evB, cudaEventDisableTiming);
    }

    init_kernel<<<(N_NODES + 255) / 256, 256>>>();
    degree_kernel<<<(E + 255) / 256, 256>>>(src, dst, E);
    cudaEventRecord(evA, 0);

    // Branch: scan + permute (need deg_in) run concurrently with gemm (needs deg_out).
    cudaStreamWaitEvent(s2, evA, 0);
    scan_kernel<<<N_CHUNKS, 256, 0, s2>>>();
    permute_kernel<<<(E + 255) / 256, 256, 0, s2>>>(src, dst, E);
    cudaEventRecord(evB, s2);

    gemm_scale_kernel<<<(N_NODES + 127) / 128, 256>>>(x, W);

    cudaStreamWaitEvent(0, evB, 0);
    aggregate_kernel<<<(N_NODES * 32 + 255) / 256, 256>>>(b, out);
}

// round 10
// speedup vs baseline: 1.4593x; 1.4593x over previous
#include <cuda_runtime.h>
#include <cuda_bf16.h>
#include <cstdint>

#define N_NODES 100000
#define E_MAX   1200000
#define D 64

#define SCAN_CHUNK 1024
#define N_CHUNKS   ((N_NODES + SCAN_CHUNK - 1) / SCAN_CHUNK)   // 98
#define N_PADDED   (N_CHUNKS * SCAN_CHUNK)                     // 100352

// Device scratch (no allocations allowed).
__device__ float g_h[N_NODES * D];              // (x@W) * norm_src, 25.6 MB
__device__ int   g_deg_out[N_NODES];
__device__ int   g_deg_in[N_NODES];
__device__ int   g_rowptr[N_PADDED + 1];
__device__ int   g_cursor[N_NODES];
__device__ int   g_scan_val[N_CHUNKS];          // -1 = not published, else chunk sum
__device__ int   g_csrc[E_MAX];                 // src node per CSR slot (grouped by dst)

// ---------------------------------------------------------------------------
__global__ void init_kernel() {
    int i = blockIdx.x * blockDim.x + threadIdx.x;
    if (i < N_NODES) { g_deg_out[i] = 0; g_deg_in[i] = 0; }
    if (i < N_CHUNKS) g_scan_val[i] = -1;
}

// ---------------------------------------------------------------------------
__global__ void degree_kernel(const int* __restrict__ src,
                              const int* __restrict__ dst, int E) {
    int i = blockIdx.x * blockDim.x + threadIdx.x;
    if (i < E) {
        atomicAdd(&g_deg_out[src[i]], 1);
        atomicAdd(&g_deg_in [dst[i]], 1);
    }
}

// ---------------------------------------------------------------------------
// Single-pass exclusive scan of deg_in with decoupled lookback (98 blocks, one wave).
__global__ void __launch_bounds__(256) scan_kernel() {
    __shared__ int sh[256];
    const int t    = threadIdx.x;
    const int bid  = blockIdx.x;
    const int base = bid * SCAN_CHUNK + t * 4;

    int v0 = (base + 0 < N_NODES) ? g_deg_in[base + 0] : 0;
    int v1 = (base + 1 < N_NODES) ? g_deg_in[base + 1] : 0;
    int v2 = (base + 2 < N_NODES) ? g_deg_in[base + 2] : 0;
    int v3 = (base + 3 < N_NODES) ? g_deg_in[base + 3] : 0;
    int s  = v0 + v1 + v2 + v3;

    sh[t] = s; __syncthreads();
    #pragma unroll
    for (int off = 1; off < 256; off <<= 1) {
        int x = (t >= off) ? sh[t - off] : 0;
        __syncthreads();
        sh[t] += x;
        __syncthreads();
    }
    const int excl = sh[t] - s;
    if (t == 255) atomicExch(&g_scan_val[bid], sh[255]);

    int part = 0;
    if (t < bid) {
        int v;
        do { v = atomicAdd(&g_scan_val[t], 0); } while (v < 0);
        part = v;
    }
    __syncthreads();
    sh[t] = part; __syncthreads();
    #pragma unroll
    for (int off = 128; off > 0; off >>= 1) {
        if (t < off) sh[t] += sh[t + off];
        __syncthreads();
    }
    const int off0 = sh[0];

    int r0 = off0 + excl;
    g_rowptr[base + 0] = r0;
    g_rowptr[base + 1] = r0 + v0;
    g_rowptr[base + 2] = r0 + v0 + v1;
    g_rowptr[base + 3] = r0 + v0 + v1 + v2;
    if (base + 0 < N_NODES) g_cursor[base + 0] = r0;
    if (base + 1 < N_NODES) g_cursor[base + 1] = r0 + v0;
    if (base + 2 < N_NODES) g_cursor[base + 2] = r0 + v0 + v1;
    if (base + 3 < N_NODES) g_cursor[base + 3] = r0 + v0 + v1 + v2;
}

// ---------------------------------------------------------------------------
__global__ void permute_kernel(const int* __restrict__ src,
                               const int* __restrict__ dst, int E) {
    int i = blockIdx.x * blockDim.x + threadIdx.x;
    if (i < E) {
        int slot = atomicAdd(&g_cursor[dst[i]], 1);
        g_csrc[slot] = src[i];
    }
}

// ---------------------------------------------------------------------------
// Tensor-core GEMM: h_scaled = (x @ W) * norm_src, bf16 hi/lo split (3 MMA passes).
// Block: 256 threads (8 warps), tile 256 rows. Warp: 32 rows x 64 cols.
#define TILE_M   256
#define A_STRIDE 72                       // bf16 elems per row (144 B, 16B-aligned, conflict-free)
#define SM_AS_HI 0
#define SM_AS_LO (TILE_M * A_STRIDE * 2)                  // 36864
#define SM_WS_HI (SM_AS_LO + TILE_M * A_STRIDE * 2)       // 73728
#define SM_WS_LO (SM_WS_HI + 64 * A_STRIDE * 2)           // 82944
#define SM_TOTAL (SM_WS_LO + 64 * A_STRIDE * 2)           // 92160

__device__ __forceinline__ void ldsm_x4(uint32_t r[4], uint32_t addr) {
    asm volatile("ldmatrix.sync.aligned.m8n8.x4.shared.b16 {%0,%1,%2,%3}, [%4];"
                 : "=r"(r[0]), "=r"(r[1]), "=r"(r[2]), "=r"(r[3]) : "r"(addr));
}
__device__ __forceinline__ void ldsm_x2t(uint32_t r[2], uint32_t addr) {
    asm volatile("ldmatrix.sync.aligned.m8n8.x2.trans.shared.b16 {%0,%1}, [%2];"
                 : "=r"(r[0]), "=r"(r[1]) : "r"(addr));
}
__device__ __forceinline__ void mma_bf16(float c[4], const uint32_t a[4], const uint32_t b[2]) {
    asm volatile("mma.sync.aligned.m16n8k16.row.col.f32.bf16.bf16.f32 "
                 "{%0,%1,%2,%3}, {%4,%5,%6,%7}, {%8,%9}, {%0,%1,%2,%3};"
                 : "+f"(c[0]), "+f"(c[1]), "+f"(c[2]), "+f"(c[3])
                 : "r"(a[0]), "r"(a[1]), "r"(a[2]), "r"(a[3]), "r"(b[0]), "r"(b[1]));
}
__device__ __forceinline__ void split_bf16(float v, __nv_bfloat16& hi, __nv_bfloat16& lo) {
    hi = __float2bfloat16(v);
    lo = __float2bfloat16(v - __bfloat162float(hi));
}

__global__ void __launch_bounds__(256) gemm_tc_kernel(const float* __restrict__ x,
                                                      const float* __restrict__ W) {
    extern __shared__ char smem[];
    __nv_bfloat16* As_hi = (__nv_bfloat16*)(smem + SM_AS_HI);
    __nv_bfloat16* As_lo = (__nv_bfloat16*)(smem + SM_AS_LO);
    __nv_bfloat16* Ws_hi = (__nv_bfloat16*)(smem + SM_WS_HI);
    __nv_bfloat16* Ws_lo = (__nv_bfloat16*)(smem + SM_WS_LO);

    const int t    = threadIdx.x;
    const int warp = t >> 5;
    const int lane = t & 31;
    const int row0 = blockIdx.x * TILE_M;

    // Stage W hi/lo: 4096 elems / 256 threads = 16 each.
    #pragma unroll
    for (int i = 0; i < 16; i++) {
        int idx = t + i * 256;
        int k = idx >> 6, n = idx & 63;
        __nv_bfloat16 hi, lo;
        split_bf16(W[idx], hi, lo);
        Ws_hi[k * A_STRIDE + n] = hi;
        Ws_lo[k * A_STRIDE + n] = lo;
    }
    // Stage x tile hi/lo: 4096 float4 / 256 threads = 16 each.
    {
        const float4* xg = (const float4*)(x + (size_t)row0 * 64);
        #pragma unroll
        for (int i = 0; i < 16; i++) {
            int idx4 = t + i * 256;          // 0..4095
            int r  = idx4 >> 4;              // 0..255
            int c4 = (idx4 & 15) * 4;
            float4 v = (row0 + r < N_NODES) ? xg[idx4]
                                            : make_float4(0.f, 0.f, 0.f, 0.f);
            __nv_bfloat16 h0,l0,h1,l1,h2,l2,h3,l3;
            split_bf16(v.x, h0, l0); split_bf16(v.y, h1, l1);
            split_bf16(v.z, h2, l2); split_bf16(v.w, h3, l3);
            __nv_bfloat16* ph = As_hi + r * A_STRIDE + c4;
            __nv_bfloat16* pl = As_lo + r * A_STRIDE + c4;
            ph[0]=h0; ph[1]=h1; ph[2]=h2; ph[3]=h3;
            pl[0]=l0; pl[1]=l1; pl[2]=l2; pl[3]=l3;
        }
    }
    __syncthreads();

    const int m_warp = warp * 32;           // this warp's rows within the tile

    float acc[2][8][4];
    #pragma unroll
    for (int mi = 0; mi < 2; mi++)
        #pragma unroll
        for (int ni = 0; ni < 8; ni++)
            #pragma unroll
            for (int q = 0; q < 4; q++) acc[mi][ni][q] = 0.f;

    const uint32_t as_hi_base = (uint32_t)__cvta_generic_to_shared(As_hi);
    const uint32_t as_lo_base = (uint32_t)__cvta_generic_to_shared(As_lo);
    const uint32_t ws_hi_base = (uint32_t)__cvta_generic_to_shared(Ws_hi);
    const uint32_t ws_lo_base = (uint32_t)__cvta_generic_to_shared(Ws_lo);

    #pragma unroll
    for (int ks = 0; ks < 4; ks++) {
        const int k0 = ks * 16;
        uint32_t a_hi[2][4], a_lo[2][4];
        #pragma unroll
        for (int mi = 0; mi < 2; mi++) {
            int r = m_warp + mi * 16 + (lane & 15);
            int c = k0 + ((lane >> 4) << 3);
            uint32_t off = (uint32_t)(r * A_STRIDE + c) * 2;
            ldsm_x4(a_hi[mi], as_hi_base + off);
            ldsm_x4(a_lo[mi], as_lo_base + off);
        }
        uint32_t b_hi[8][2], b_lo[8][2];
        #pragma unroll
        for (int ni = 0; ni < 8; ni++) {
            int kr = k0 + (lane & 15);       // lanes 0-15 supply addresses
            uint32_t off = (uint32_t)(kr * A_STRIDE + ni * 8) * 2;
            ldsm_x2t(b_hi[ni], ws_hi_base + off);
            ldsm_x2t(b_lo[ni], ws_lo_base + off);
        }
        #pragma unroll
        for (int mi = 0; mi < 2; mi++)
            #pragma unroll
            for (int ni = 0; ni < 8; ni++) {
                mma_bf16(acc[mi][ni], a_hi[mi], b_hi[ni]);
                mma_bf16(acc[mi][ni], a_hi[mi], b_lo[ni]);
                mma_bf16(acc[mi][ni], a_lo[mi], b_hi[ni]);
            }
    }

    // Epilogue: scale by rsqrt(max(deg_out,1)) and store.
    #pragma unroll
    for (int mi = 0; mi < 2; mi++) {
        int r0g = row0 + m_warp + mi * 16 + (lane >> 2);
        int r1g = r0g + 8;
        float n0 = (r0g < N_NODES) ? rsqrtf(fmaxf((float)g_deg_out[r0g], 1.f)) : 0.f;
        float n1 = (r1g < N_NODES) ? rsqrtf(fmaxf((float)g_deg_out[r1g], 1.f)) : 0.f;
        #pragma unroll
        for (int ni = 0; ni < 8; ni++) {
            int col = ni * 8 + (lane & 3) * 2;
            if (r0g < N_NODES) {
                float2 v0; v0.x = acc[mi][ni][0] * n0; v0.y = acc[mi][ni][1] * n0;
                *(float2*)(g_h + (size_t)r0g * 64 + col) = v0;
            }
            if (r1g < N_NODES) {
                float2 v1; v1.x = acc[mi][ni][2] * n1; v1.y = acc[mi][ni][3] * n1;
                *(float2*)(g_h + (size_t)r1g * 64 + col) = v1;
            }
        }
    }
}

// ---------------------------------------------------------------------------
// Pull aggregation: one warp per dst node, lane owns 2 cols. 4-deep MLP.
__global__ void __launch_bounds__(256) aggregate_kernel(const float* __restrict__ b,
                                                        float* __restrict__ out) {
    int wg   = (blockIdx.x * blockDim.x + threadIdx.x) >> 5;
    int lane = threadIdx.x & 31;
    if (wg >= N_NODES) return;

    const int beg = g_rowptr[wg];
    const int end = g_rowptr[wg + 1];

    float2 acc0 = make_float2(0.f, 0.f);
    float2 acc1 = make_float2(0.f, 0.f);

    for (int j = beg; j < end; j += 32) {
        int n  = min(32, end - j);
        int sv = (lane < n) ? g_csrc[j + lane] : 0;
        int i  = 0;
        for (; i + 4 <= n; i += 4) {
            int u0 = __shfl_sync(0xffffffff, sv, i);
            int u1 = __shfl_sync(0xffffffff, sv, i + 1);
            int u2 = __shfl_sync(0xffffffff, sv, i + 2);
            int u3 = __shfl_sync(0xffffffff, sv, i + 3);
            float2 h0 = __ldg((const float2*)(g_h + (size_t)u0 * 64) + lane);
            float2 h1 = __ldg((const float2*)(g_h + (size_t)u1 * 64) + lane);
            float2 h2 = __ldg((const float2*)(g_h + (size_t)u2 * 64) + lane);
            float2 h3 = __ldg((const float2*)(g_h + (size_t)u3 * 64) + lane);
            acc0.x += h0.x; acc0.y += h0.y;
            acc1.x += h1.x; acc1.y += h1.y;
            acc0.x += h2.x; acc0.y += h2.y;
            acc1.x += h3.x; acc1.y += h3.y;
        }
        for (; i < n; i++) {
            int u = __shfl_sync(0xffffffff, sv, i);
            float2 h = __ldg((const float2*)(g_h + (size_t)u * 64) + lane);
            acc0.x += h.x; acc0.y += h.y;
        }
    }

    float  norm = rsqrtf(fmaxf((float)(end - beg), 1.f));
    float2 bb   = *(const float2*)(b + lane * 2);
    float2 r;
    r.x = fmaxf((acc0.x + acc1.x) * norm + bb.x, 0.f);
    r.y = fmaxf((acc0.y + acc1.y) * norm + bb.y, 0.f);
    *(float2*)(out + (size_t)wg * 64 + lane * 2) = r;
}

// ---------------------------------------------------------------------------
extern "C" void kernel_launch(void* const* d_in, const int* in_sizes, int n_in,
                              void* d_out, int out_size) {
    const float* x   = (const float*)d_in[0];
    const float* W   = (const float*)d_in[1];
    const float* b   = (const float*)d_in[2];
    const int*   src = (const int*)  d_in[3];
    const int*   dst = (const int*)  d_in[4];
    const int    E   = in_sizes[3];

    float* out = (float*)d_out;

    static cudaStream_t s2 = nullptr;
    static cudaEvent_t  evA = nullptr, evB = nullptr;
    if (s2 == nullptr) {
        cudaStreamCreateWithFlags(&s2, cudaStreamNonBlocking);
        cudaEventCreateWithFlags(&evA, cudaEventDisableTiming);
        cudaEventCreateWithFlags(&evB, cudaEventDisableTiming);
        cudaFuncSetAttribute(gemm_tc_kernel,
                             cudaFuncAttributeMaxDynamicSharedMemorySize, SM_TOTAL);
    }

    init_kernel<<<(N_NODES + 255) / 256, 256>>>();
    degree_kernel<<<(E + 255) / 256, 256>>>(src, dst, E);
    cudaEventRecord(evA, 0);

    // Branch: scan + permute (need deg_in) run concurrently with gemm (needs deg_out).
    cudaStreamWaitEvent(s2, evA, 0);
    scan_kernel<<<N_CHUNKS, 256, 0, s2>>>();
    permute_kernel<<<(E + 255) / 256, 256, 0, s2>>>(src, dst, E);
    cudaEventRecord(evB, s2);

    gemm_tc_kernel<<<(N_NODES + TILE_M - 1) / TILE_M, 256, SM_TOTAL>>>(x, W);

    cudaStreamWaitEvent(0, evB, 0);
    aggregate_kernel<<<(N_NODES * 32 + 255) / 256, 256>>>(b, out);
}